// round 16
// baseline (speedup 1.0000x reference)
#include <cuda_runtime.h>
#include <cuda_fp16.h>
#include <cstdint>
#include <cstddef>

#define BSZ   8192
#define DIM   1024
#define NEXP  8
#define DDIM  4096
#define KQ    1024

// ---------------- device scratch ----------------
__device__ __align__(256) __half g_xh  [BSZ * DIM];
__device__ __align__(256) __half g_w1h [DIM * DIM];
__device__ __align__(256) __half g_fc1h[NEXP * DDIM * DIM];
__device__ __align__(256) __half g_fc2h[(size_t)NEXP * DIM * DDIM];
__device__ __align__(256) __half g_Yh  [NEXP * KQ * DIM];
__device__ __align__(256) __half g_Hh  [(size_t)NEXP * KQ * DDIM];
__device__ __align__(256) float g_scores[BSZ * NEXP];
__device__ __align__(256) float g_logits[BSZ * NEXP];
__device__ __align__(256) unsigned char g_mask[BSZ * NEXP];
__device__ __align__(256) int   g_rlist[NEXP * KQ];
__device__ __align__(256) float g_wlist[NEXP * KQ];
__device__                int   g_cnt[NEXP];

// ---------------- helpers ----------------
__device__ __forceinline__ float gelu_tanh(float x) {
    float x3 = x * x * x;
    return 0.5f * x * (1.0f + tanhf(0.7978845608028654f * (x + 0.044715f * x3)));
}
__device__ __forceinline__ void cp16(uint32_t saddr, const void* g) {
    asm volatile("cp.async.cg.shared.global [%0], [%1], 16;\n" :: "r"(saddr), "l"(g));
}
#define CPC()    asm volatile("cp.async.commit_group;\n" ::)
#define CPW1()   asm volatile("cp.async.wait_group 1;\n" ::: "memory")

__device__ __forceinline__ uint32_t smem_u32(const void* p) {
    uint32_t a;
    asm("{ .reg .u64 t; cvta.to.shared.u64 t, %1; cvt.u32.u64 %0, t; }" : "=r"(a) : "l"(p));
    return a;
}
__device__ __forceinline__ void ldsm4(uint32_t* r, uint32_t saddr) {
    asm volatile("ldmatrix.sync.aligned.m8n8.x4.shared.b16 {%0,%1,%2,%3}, [%4];"
                 : "=r"(r[0]), "=r"(r[1]), "=r"(r[2]), "=r"(r[3]) : "r"(saddr));
}
__device__ __forceinline__ void mma_f16(float* c, const uint32_t* a, uint32_t b0, uint32_t b1) {
    asm volatile("mma.sync.aligned.m16n8k16.row.col.f32.f16.f16.f32 "
        "{%0,%1,%2,%3}, {%4,%5,%6,%7}, {%8,%9}, {%0,%1,%2,%3};"
        : "+f"(c[0]), "+f"(c[1]), "+f"(c[2]), "+f"(c[3])
        : "r"(a[0]), "r"(a[1]), "r"(a[2]), "r"(a[3]), "r"(b0), "r"(b1));
}

__device__ __forceinline__ void cvt8(const float* __restrict__ in, __half* __restrict__ out, int i) {
    float4 a = ((const float4*)in)[2 * i];
    float4 b = ((const float4*)in)[2 * i + 1];
    __half2 h[4];
    h[0] = __floats2half2_rn(a.x, a.y);
    h[1] = __floats2half2_rn(a.z, a.w);
    h[2] = __floats2half2_rn(b.x, b.y);
    h[3] = __floats2half2_rn(b.z, b.w);
    ((uint4*)out)[i] = *(const uint4*)h;
}

// ---------------- unified streaming kernel: ALL pure-bandwidth work in one launch ----------
// sections: [x: cvt->xh + copy->out] [fc1s->fc1h] [fc2s->fc2h] [cp_w1->w1h]
#define N8_X   (BSZ * DIM / 8)
#define N8_FC1 (NEXP * DDIM * DIM / 8)
#define N8_FC2 (NEXP * DIM * DDIM / 8)
#define N8_W1  (DIM * DIM / 8)

__global__ void __launch_bounds__(256) stream_kernel(
    const float* __restrict__ x, float* __restrict__ out,
    const float* __restrict__ fc1s, const float* __restrict__ fc2s,
    const float* __restrict__ cp_w1)
{
    const int total = N8_X + N8_FC1 + N8_FC2 + N8_W1;
    for (int i = blockIdx.x * 256 + threadIdx.x; i < total; i += gridDim.x * 256) {
        if (i < N8_X) {
            float4 a = ((const float4*)x)[2 * i];
            float4 b = ((const float4*)x)[2 * i + 1];
            ((float4*)out)[2 * i]     = a;
            ((float4*)out)[2 * i + 1] = b;
            __half2 h[4];
            h[0] = __floats2half2_rn(a.x, a.y);
            h[1] = __floats2half2_rn(a.z, a.w);
            h[2] = __floats2half2_rn(b.x, b.y);
            h[3] = __floats2half2_rn(b.z, b.w);
            ((uint4*)g_xh)[i] = *(const uint4*)h;
        } else if (i < N8_X + N8_FC1) {
            cvt8(fc1s, g_fc1h, i - N8_X);
        } else if (i < N8_X + N8_FC1 + N8_FC2) {
            cvt8(fc2s, g_fc2h, i - N8_X - N8_FC1);
        } else {
            cvt8(cp_w1, g_w1h, i - N8_X - N8_FC1 - N8_FC2);
        }
    }
}

// ---------------- scores: dot product + logits zero only (bandwidth work moved out) --------
__global__ void scores_kernel(const float* __restrict__ x, const float* __restrict__ Wg) {
    int row = blockIdx.x, tid = threadIdx.x, lane = tid & 31, wid = tid >> 5;
    __shared__ float4 xs[DIM / 4];
    xs[tid] = ((const float4*)(x + (size_t)row * DIM))[tid];
    if (lane == 0) g_logits[row * NEXP + wid] = 0.0f;
    __syncthreads();
    const float4* wg = (const float4*)(Wg + wid * DIM);
    float s = 0.f;
    #pragma unroll
    for (int i = lane; i < DIM / 4; i += 32) {
        float4 xv = xs[i];
        float4 wv = __ldg(&wg[i]);
        s += xv.x * wv.x + xv.y * wv.y + xv.z * wv.z + xv.w * wv.w;
    }
    #pragma unroll
    for (int o = 16; o; o >>= 1) s += __shfl_xor_sync(0xFFFFFFFFu, s, o);
    if (lane == 0) g_scores[row * NEXP + wid] = 0.5f * (tanhf(s) + 1.0f);
}

__global__ void topk_kernel() {
    int j = blockIdx.x, tid = threadIdx.x;
    __shared__ unsigned keys[BSZ];
    __shared__ int hist[256], eqscan[256];
    __shared__ int sbin, sneed;
    if (tid == 0) g_cnt[j] = 0;
    for (int i = tid; i < BSZ; i += 256) {
        keys[i] = __float_as_uint(g_scores[i * NEXP + j]);
        g_mask[i * NEXP + j] = 0;
    }
    __syncthreads();
    unsigned prefix = 0; int need = KQ;
    for (int shift = 24; shift >= 0; shift -= 8) {
        hist[tid] = 0;
        __syncthreads();
        unsigned hmask = (shift == 24) ? 0u : (0xFFFFFFFFu << (shift + 8));
        for (int i = tid; i < BSZ; i += 256) {
            unsigned kv = keys[i];
            if ((kv & hmask) == prefix) atomicAdd(&hist[(kv >> shift) & 255], 1);
        }
        __syncthreads();
        if (tid == 0) {
            int cum = 0;
            for (int b = 255; b >= 0; b--) {
                cum += hist[b];
                if (cum >= need) { sbin = b; sneed = need - (cum - hist[b]); break; }
            }
        }
        __syncthreads();
        prefix |= ((unsigned)sbin) << shift;
        need = sneed;
        __syncthreads();
    }
    unsigned T = prefix;
    int base = tid * 32, ceq = 0;
    for (int i = base; i < base + 32; i++) if (keys[i] == T) ceq++;
    eqscan[tid] = ceq;
    __syncthreads();
    if (tid == 0) { int run = 0; for (int t = 0; t < 256; t++) { int c = eqscan[t]; eqscan[t] = run; run += c; } }
    __syncthreads();
    int rank = eqscan[tid];
    for (int i = base; i < base + 32; i++) {
        unsigned kv = keys[i];
        bool keep = (kv > T);
        if (kv == T) { keep = (rank < need); rank++; }
        if (keep) {
            g_mask[i * NEXP + j] = 1;
            int p = atomicAdd(&g_cnt[j], 1);
            g_rlist[j * KQ + p] = i;
            g_wlist[j * KQ + p] = __uint_as_float(kv);
        }
    }
}

__global__ void gather_ln_kernel(const float* __restrict__ x,
                                 const float* __restrict__ g, const float* __restrict__ b) {
    int blk = blockIdx.x, j = blk >> 10, slot = blk & 1023;
    int r = g_rlist[j * KQ + slot];
    int tid = threadIdx.x, lane = tid & 31, wid = tid >> 5;
    float4 v = ((const float4*)(x + (size_t)r * DIM))[tid];
    float s = v.x + v.y + v.z + v.w;
    float q = v.x * v.x + v.y * v.y + v.z * v.z + v.w * v.w;
    #pragma unroll
    for (int o = 16; o; o >>= 1) { s += __shfl_xor_sync(~0u, s, o); q += __shfl_xor_sync(~0u, q, o); }
    __shared__ float red[16];
    __shared__ float mu_s, rs_s;
    if (lane == 0) { red[wid] = s; red[wid + 8] = q; }
    __syncthreads();
    if (tid == 0) {
        float S = 0.f, Q = 0.f;
        for (int w = 0; w < 8; w++) { S += red[w]; Q += red[w + 8]; }
        float mu = S * (1.0f / DIM);
        mu_s = mu; rs_s = rsqrtf(Q * (1.0f / DIM) - mu * mu + 1e-5f);
    }
    __syncthreads();
    float mu = mu_s, rs = rs_s;
    float4 gv = ((const float4*)g)[tid], bv = ((const float4*)b)[tid];
    __half2* Yp = (__half2*)(g_Yh + ((size_t)j * KQ + slot) * DIM);
    Yp[tid * 2]     = __floats2half2_rn((v.x - mu) * rs * gv.x + bv.x, (v.y - mu) * rs * gv.y + bv.y);
    Yp[tid * 2 + 1] = __floats2half2_rn((v.z - mu) * rs * gv.z + bv.z, (v.w - mu) * rs * gv.w + bv.w);
}

// ---------------- fp16 TN GEMM body: 128x128 CTA tile, 32x64 warp tiles (4x2 warps), 256 thr ----
// k-chunk = 64 halfs, 3-slot smem ring, one __syncthreads per iter, 2 CTAs/SM => 16 warps/SM.
#define SLOT_B  36864
#define SMEM_GM (4096 + 3 * SLOT_B)

template<int MODE>
__device__ __forceinline__ void gemm_body(
    unsigned char* smem,
    const __half* __restrict__ A, const __half* __restrict__ B, int N, int K,
    const float* __restrict__ bias,
    __half* __restrict__ Hout,
    const int* __restrict__ rl, const float* __restrict__ wl, float* __restrict__ outAdd,
    const float* __restrict__ w2, float* __restrict__ logits,
    int bm, int bn)
{
    const uint32_t su = smem_u32(smem);
    const int tid = threadIdx.x, lane = tid & 31, wid = tid >> 5;
    const int mw = wid >> 1, nw = wid & 1;          // 4x2 warps, warp tile 32x64

    if (MODE == 2) {
        float* w2s = (float*)smem;   // [8][128]
        #pragma unroll
        for (int i = 0; i < 4; i++) {
            int idx = tid + i * 256;
            w2s[idx] = w2[(idx >> 7) * DIM + bn + (idx & 127)];
        }
    }

    float acc[2][8][4] = {};

    auto fill = [&](int chunk, int s) {
        uint32_t sa = su + 4096 + s * SLOT_B;
        uint32_t sb = sa + 18432;
        const __half* Ap = A + (size_t)bm * K + chunk * 64;
        const __half* Bp = B + (size_t)bn * K + chunk * 64;
        #pragma unroll
        for (int i = 0; i < 4; i++) {
            int id = tid + i * 256;                 // 0..1023
            int row = id >> 3, c = (id & 7) * 8;    // halfs
            cp16(sa + row * 144 + c * 2, Ap + (size_t)row * K + c);
            cp16(sb + row * 144 + c * 2, Bp + (size_t)row * K + c);
        }
    };

    const int nk = K >> 6;                          // 64-half K chunks
    fill(0, 0); CPC();
    fill(1, 1); CPC();

    const int lr16 = lane & 15, lhi = (lane >> 4) * 8;

    for (int kt = 0; kt < nk; kt++) {
        int s = kt % 3;
        CPW1();
        __syncthreads();            // slot s ready; slot (kt+2)%3 = (kt-1)%3 free
        if (kt + 2 < nk) fill(kt + 2, (kt + 2) % 3);
        CPC();
        uint32_t sa = su + 4096 + s * SLOT_B;
        uint32_t sb = sa + 18432;
        #pragma unroll
        for (int ks = 0; ks < 4; ks++) {
            const int kk = ks * 16;
            uint32_t af[2][4], bq[4][4];
            #pragma unroll
            for (int mt = 0; mt < 2; mt++)
                ldsm4(af[mt], sa + (mw * 32 + mt * 16 + lr16) * 144 + (kk + lhi) * 2);
            #pragma unroll
            for (int p = 0; p < 4; p++)
                ldsm4(bq[p], sb + (nw * 64 + p * 16 + lr16) * 144 + (kk + lhi) * 2);
            #pragma unroll
            for (int mt = 0; mt < 2; mt++)
                #pragma unroll
                for (int p = 0; p < 4; p++) {
                    mma_f16(acc[mt][2 * p],     af[mt], bq[p][0], bq[p][2]);
                    mma_f16(acc[mt][2 * p + 1], af[mt], bq[p][1], bq[p][3]);
                }
        }
    }

    const int lane4 = lane & 3, lrow = lane >> 2;

    if (MODE == 0) {
        #pragma unroll
        for (int mt = 0; mt < 2; mt++) {
            int r0 = bm + mw * 32 + mt * 16 + lrow;
            #pragma unroll
            for (int nt = 0; nt < 8; nt++) {
                int gn = bn + nw * 64 + nt * 8 + lane4 * 2;
                float* a = acc[mt][nt];
                float b0 = bias[gn], b1 = bias[gn + 1];
                *(__half2*)(Hout + (size_t)r0 * N + gn) =
                    __floats2half2_rn(gelu_tanh(a[0] + b0), gelu_tanh(a[1] + b1));
                *(__half2*)(Hout + (size_t)(r0 + 8) * N + gn) =
                    __floats2half2_rn(gelu_tanh(a[2] + b0), gelu_tanh(a[3] + b1));
            }
        }
    } else if (MODE == 1) {
        #pragma unroll
        for (int mt = 0; mt < 2; mt++) {
            int gr = bm + mw * 32 + mt * 16 + lrow;
            int i0 = rl[gr], i1 = rl[gr + 8];
            float w0 = wl[gr], w1 = wl[gr + 8];
            #pragma unroll
            for (int nt = 0; nt < 8; nt++) {
                int gn = bn + nw * 64 + nt * 8 + lane4 * 2;
                float* a = acc[mt][nt];
                float b0 = bias[gn], b1 = bias[gn + 1];
                atomicAdd(&outAdd[(size_t)i0 * DIM + gn],     (a[0] + b0) * w0);
                atomicAdd(&outAdd[(size_t)i0 * DIM + gn + 1], (a[1] + b1) * w0);
                atomicAdd(&outAdd[(size_t)i1 * DIM + gn],     (a[2] + b0) * w1);
                atomicAdd(&outAdd[(size_t)i1 * DIM + gn + 1], (a[3] + b1) * w1);
            }
        }
    } else {
        const float* w2s = (const float*)smem;
        #pragma unroll
        for (int mt = 0; mt < 2; mt++) {
            #pragma unroll
            for (int half = 0; half < 2; half++) {
                int gr = bm + mw * 32 + mt * 16 + lrow + half * 8;
                float part[NEXP] = {};
                #pragma unroll
                for (int nt = 0; nt < 8; nt++) {
                    int cn = nw * 64 + nt * 8 + lane4 * 2;
                    float h0 = gelu_tanh(acc[mt][nt][2 * half]     + bias[bn + cn]);
                    float h1 = gelu_tanh(acc[mt][nt][2 * half + 1] + bias[bn + cn + 1]);
                    #pragma unroll
                    for (int e = 0; e < NEXP; e++)
                        part[e] += h0 * w2s[e * 128 + cn] + h1 * w2s[e * 128 + cn + 1];
                }
                #pragma unroll
                for (int e = 0; e < NEXP; e++) {
                    part[e] += __shfl_xor_sync(~0u, part[e], 1);
                    part[e] += __shfl_xor_sync(~0u, part[e], 2);
                }
                if (lane4 == 0)
                    #pragma unroll
                    for (int e = 0; e < NEXP; e++)
                        atomicAdd(&logits[gr * NEXP + e], part[e]);
            }
        }
    }
}

// fc1: H = gelu(Y @ fc1^T + b1s) per expert. grid (32, 8, 8)
__global__ void __launch_bounds__(256, 2) gemm_fc1(
    const __half* __restrict__ Y, const __half* __restrict__ fc1,
    const float* __restrict__ b1s, __half* __restrict__ H)
{
    extern __shared__ __align__(16) unsigned char smem[];
    int z = blockIdx.z;
    gemm_body<0>(smem,
        Y + (size_t)z * KQ * DIM, fc1 + (size_t)z * DDIM * DIM, DDIM, DIM,
        b1s + (size_t)z * DDIM,
        H + (size_t)z * KQ * DDIM,
        nullptr, nullptr, nullptr, nullptr, nullptr,
        blockIdx.y * 128, blockIdx.x * 128);
}

// combined fc2 (bid<512) + cap-loss GEMM (bid>=512). grid 1024 x 1D
__global__ void __launch_bounds__(256, 2) gemm_combo(
    const __half* __restrict__ H, const __half* __restrict__ fc2,
    const float* __restrict__ b2s, float* __restrict__ out,
    const __half* __restrict__ xh, const __half* __restrict__ w1h,
    const float* __restrict__ cp_b1, const float* __restrict__ cp_w2)
{
    extern __shared__ __align__(16) unsigned char smem[];
    int bid = blockIdx.x;
    if (bid < 512) {
        int z = bid >> 6, by = (bid >> 3) & 7, bx = bid & 7;
        gemm_body<1>(smem,
            H + (size_t)z * KQ * DDIM, fc2 + (size_t)z * DIM * DDIM, DIM, DDIM,
            b2s + (size_t)z * DIM,
            nullptr,
            g_rlist + z * KQ, g_wlist + z * KQ, out, nullptr, nullptr,
            by * 128, bx * 128);
    } else {
        int t = bid - 512, by = t >> 3, bx = t & 7;
        gemm_body<2>(smem,
            xh, w1h, DIM, DIM,
            cp_b1,
            nullptr,
            nullptr, nullptr, nullptr, cp_w2, g_logits,
            by * 128, bx * 128);
    }
}

__global__ void __launch_bounds__(1024) loss_kernel(const float* __restrict__ cp_b2,
                                                    float* __restrict__ out_loss) {
    int tid = threadIdx.x;
    float s = 0.f;
    for (int i = tid; i < BSZ * NEXP; i += 1024) {
        float l = g_logits[i] + cp_b2[i & 7];
        float sp = fmaxf(l, 0.f) + log1pf(expf(-fabsf(l)));
        s += sp - l * (float)g_mask[i];
    }
    __shared__ float red[1024];
    red[tid] = s;
    __syncthreads();
    for (int o = 512; o; o >>= 1) { if (tid < o) red[tid] += red[tid + o]; __syncthreads(); }
    if (tid == 0) out_loss[0] = red[0] * (1.0f / (BSZ * NEXP));
}

extern "C" void kernel_launch(void* const* d_in, const int* in_sizes, int n_in,
                              void* d_out, int out_size) {
    const float* x     = (const float*)d_in[0];
    const float* Wg    = (const float*)d_in[1];
    const float* cp_w1 = (const float*)d_in[2];
    const float* cp_b1 = (const float*)d_in[3];
    const float* cp_w2 = (const float*)d_in[4];
    const float* cp_b2 = (const float*)d_in[5];
    const float* ln_g  = (const float*)d_in[6];
    const float* ln_b  = (const float*)d_in[7];
    const float* fc1s  = (const float*)d_in[8];
    const float* b1s   = (const float*)d_in[9];
    const float* fc2s  = (const float*)d_in[10];
    const float* b2s   = (const float*)d_in[11];
    float* out = (float*)d_out;

    __half *xh, *w1h, *fc1h, *fc2h, *Yh, *Hh;
    cudaGetSymbolAddress((void**)&xh,   g_xh);
    cudaGetSymbolAddress((void**)&w1h,  g_w1h);
    cudaGetSymbolAddress((void**)&fc1h, g_fc1h);
    cudaGetSymbolAddress((void**)&fc2h, g_fc2h);
    cudaGetSymbolAddress((void**)&Yh,   g_Yh);
    cudaGetSymbolAddress((void**)&Hh,   g_Hh);

    cudaFuncSetAttribute(gemm_fc1,   cudaFuncAttributeMaxDynamicSharedMemorySize, SMEM_GM);
    cudaFuncSetAttribute(gemm_combo, cudaFuncAttributeMaxDynamicSharedMemorySize, SMEM_GM);

    // one streaming launch: all conversions + out seed at ~70% of DRAM peak
    stream_kernel<<<4096, 256>>>(x, out, fc1s, fc2s, cp_w1);

    // latency chain (slimmed scores: dot + logits zero only)
    scores_kernel<<<BSZ, 256>>>(x, Wg);
    topk_kernel<<<NEXP, 256>>>();
    gather_ln_kernel<<<NEXP * KQ, 256>>>(x, ln_g, ln_b);

    // fc1: per expert H = gelu(Y @ fc1^T + b1s)  (M=1024, N=4096, K=1024)
    gemm_fc1<<<dim3(DDIM / 128, KQ / 128, NEXP), 256, SMEM_GM>>>(Yh, fc1h, b1s, Hh);

    // combined fc2 scatter-add + cap-loss logits GEMM (out seeded by stream_kernel)
    gemm_combo<<<1024, 256, SMEM_GM>>>(Hh, fc2h, b2s, out, xh, w1h, cp_b1, cp_w2);

    loss_kernel<<<1, 1024>>>(cp_b2, out + (size_t)BSZ * DIM);
    (void)in_sizes; (void)n_in; (void)out_size;
}

// round 17
// speedup vs baseline: 1.0113x; 1.0113x over previous
#include <cuda_runtime.h>
#include <cuda_fp16.h>
#include <cstdint>
#include <cstddef>

#define BSZ   8192
#define DIM   1024
#define NEXP  8
#define DDIM  4096
#define KQ    1024

// ---------------- device scratch ----------------
__device__ __align__(256) __half g_xh  [BSZ * DIM];
__device__ __align__(256) __half g_w1h [DIM * DIM];
__device__ __align__(256) __half g_fc1h[NEXP * DDIM * DIM];
__device__ __align__(256) __half g_fc2h[(size_t)NEXP * DIM * DDIM];
__device__ __align__(256) __half g_Yh  [NEXP * KQ * DIM];
__device__ __align__(256) __half g_Hh  [(size_t)NEXP * KQ * DDIM];
__device__ __align__(256) float g_scores[BSZ * NEXP];
__device__ __align__(256) float g_logits[BSZ * NEXP];
__device__ __align__(256) unsigned char g_mask[BSZ * NEXP];
__device__ __align__(256) int   g_rlist[NEXP * KQ];
__device__ __align__(256) float g_wlist[NEXP * KQ];
__device__                int   g_cnt[NEXP];

// ---------------- helpers ----------------
__device__ __forceinline__ float gelu_tanh(float x) {
    float x3 = x * x * x;
    return 0.5f * x * (1.0f + tanhf(0.7978845608028654f * (x + 0.044715f * x3)));
}
__device__ __forceinline__ void cp16(uint32_t saddr, const void* g) {
    asm volatile("cp.async.cg.shared.global [%0], [%1], 16;\n" :: "r"(saddr), "l"(g));
}
#define CPC()    asm volatile("cp.async.commit_group;\n" ::)
#define CPW1()   asm volatile("cp.async.wait_group 1;\n" ::: "memory")

__device__ __forceinline__ uint32_t smem_u32(const void* p) {
    uint32_t a;
    asm("{ .reg .u64 t; cvta.to.shared.u64 t, %1; cvt.u32.u64 %0, t; }" : "=r"(a) : "l"(p));
    return a;
}
__device__ __forceinline__ void ldsm4(uint32_t* r, uint32_t saddr) {
    asm volatile("ldmatrix.sync.aligned.m8n8.x4.shared.b16 {%0,%1,%2,%3}, [%4];"
                 : "=r"(r[0]), "=r"(r[1]), "=r"(r[2]), "=r"(r[3]) : "r"(saddr));
}
__device__ __forceinline__ void mma_f16(float* c, const uint32_t* a, uint32_t b0, uint32_t b1) {
    asm volatile("mma.sync.aligned.m16n8k16.row.col.f32.f16.f16.f32 "
        "{%0,%1,%2,%3}, {%4,%5,%6,%7}, {%8,%9}, {%0,%1,%2,%3};"
        : "+f"(c[0]), "+f"(c[1]), "+f"(c[2]), "+f"(c[3])
        : "r"(a[0]), "r"(a[1]), "r"(a[2]), "r"(a[3]), "r"(b0), "r"(b1));
}

// ---------------- conversion: 8 floats -> 8 halfs per thread, one 16B store ----------------
__global__ void cvt_kernel(const float* __restrict__ in, __half* __restrict__ out, int n8) {
    for (int i = blockIdx.x * blockDim.x + threadIdx.x; i < n8; i += gridDim.x * blockDim.x) {
        float4 a = ((const float4*)in)[2 * i];
        float4 b = ((const float4*)in)[2 * i + 1];
        __half2 h[4];
        h[0] = __floats2half2_rn(a.x, a.y);
        h[1] = __floats2half2_rn(a.z, a.w);
        h[2] = __floats2half2_rn(b.x, b.y);
        h[3] = __floats2half2_rn(b.z, b.w);
        ((uint4*)out)[i] = *(const uint4*)h;
    }
}

// ---------------- scores (+ fused x->xh cvt, x->out copy, logits zero), float4 dot ----------
__global__ void scores_kernel(const float* __restrict__ x, const float* __restrict__ Wg,
                              __half* __restrict__ xh, float* __restrict__ out) {
    int row = blockIdx.x, tid = threadIdx.x, lane = tid & 31, wid = tid >> 5;
    __shared__ float4 xs[DIM / 4];
    float4 v = ((const float4*)(x + (size_t)row * DIM))[tid];
    xs[tid] = v;
    ((float4*)(out + (size_t)row * DIM))[tid] = v;
    __half2* xp = (__half2*)(xh + (size_t)row * DIM);
    xp[tid * 2]     = __floats2half2_rn(v.x, v.y);
    xp[tid * 2 + 1] = __floats2half2_rn(v.z, v.w);
    if (lane == 0) g_logits[row * NEXP + wid] = 0.0f;
    __syncthreads();
    const float4* wg = (const float4*)(Wg + wid * DIM);
    float s = 0.f;
    #pragma unroll
    for (int i = lane; i < DIM / 4; i += 32) {
        float4 xv = xs[i];
        float4 wv = __ldg(&wg[i]);
        s += xv.x * wv.x + xv.y * wv.y + xv.z * wv.z + xv.w * wv.w;
    }
    #pragma unroll
    for (int o = 16; o; o >>= 1) s += __shfl_xor_sync(0xFFFFFFFFu, s, o);
    if (lane == 0) g_scores[row * NEXP + wid] = 0.5f * (tanhf(s) + 1.0f);
}

__global__ void topk_kernel() {
    int j = blockIdx.x, tid = threadIdx.x;
    __shared__ unsigned keys[BSZ];
    __shared__ int hist[256], eqscan[256];
    __shared__ int sbin, sneed;
    if (tid == 0) g_cnt[j] = 0;
    for (int i = tid; i < BSZ; i += 256) {
        keys[i] = __float_as_uint(g_scores[i * NEXP + j]);
        g_mask[i * NEXP + j] = 0;
    }
    __syncthreads();
    unsigned prefix = 0; int need = KQ;
    for (int shift = 24; shift >= 0; shift -= 8) {
        hist[tid] = 0;
        __syncthreads();
        unsigned hmask = (shift == 24) ? 0u : (0xFFFFFFFFu << (shift + 8));
        for (int i = tid; i < BSZ; i += 256) {
            unsigned kv = keys[i];
            if ((kv & hmask) == prefix) atomicAdd(&hist[(kv >> shift) & 255], 1);
        }
        __syncthreads();
        if (tid == 0) {
            int cum = 0;
            for (int b = 255; b >= 0; b--) {
                cum += hist[b];
                if (cum >= need) { sbin = b; sneed = need - (cum - hist[b]); break; }
            }
        }
        __syncthreads();
        prefix |= ((unsigned)sbin) << shift;
        need = sneed;
        __syncthreads();
    }
    unsigned T = prefix;
    int base = tid * 32, ceq = 0;
    for (int i = base; i < base + 32; i++) if (keys[i] == T) ceq++;
    eqscan[tid] = ceq;
    __syncthreads();
    if (tid == 0) { int run = 0; for (int t = 0; t < 256; t++) { int c = eqscan[t]; eqscan[t] = run; run += c; } }
    __syncthreads();
    int rank = eqscan[tid];
    for (int i = base; i < base + 32; i++) {
        unsigned kv = keys[i];
        bool keep = (kv > T);
        if (kv == T) { keep = (rank < need); rank++; }
        if (keep) {
            g_mask[i * NEXP + j] = 1;
            int p = atomicAdd(&g_cnt[j], 1);
            g_rlist[j * KQ + p] = i;
            g_wlist[j * KQ + p] = __uint_as_float(kv);
        }
    }
}

__global__ void gather_ln_kernel(const float* __restrict__ x,
                                 const float* __restrict__ g, const float* __restrict__ b) {
    int blk = blockIdx.x, j = blk >> 10, slot = blk & 1023;
    int r = g_rlist[j * KQ + slot];
    int tid = threadIdx.x, lane = tid & 31, wid = tid >> 5;
    float4 v = ((const float4*)(x + (size_t)r * DIM))[tid];
    float s = v.x + v.y + v.z + v.w;
    float q = v.x * v.x + v.y * v.y + v.z * v.z + v.w * v.w;
    #pragma unroll
    for (int o = 16; o; o >>= 1) { s += __shfl_xor_sync(~0u, s, o); q += __shfl_xor_sync(~0u, q, o); }
    __shared__ float red[16];
    __shared__ float mu_s, rs_s;
    if (lane == 0) { red[wid] = s; red[wid + 8] = q; }
    __syncthreads();
    if (tid == 0) {
        float S = 0.f, Q = 0.f;
        for (int w = 0; w < 8; w++) { S += red[w]; Q += red[w + 8]; }
        float mu = S * (1.0f / DIM);
        mu_s = mu; rs_s = rsqrtf(Q * (1.0f / DIM) - mu * mu + 1e-5f);
    }
    __syncthreads();
    float mu = mu_s, rs = rs_s;
    float4 gv = ((const float4*)g)[tid], bv = ((const float4*)b)[tid];
    __half2* Yp = (__half2*)(g_Yh + ((size_t)j * KQ + slot) * DIM);
    Yp[tid * 2]     = __floats2half2_rn((v.x - mu) * rs * gv.x + bv.x, (v.y - mu) * rs * gv.y + bv.y);
    Yp[tid * 2 + 1] = __floats2half2_rn((v.z - mu) * rs * gv.z + bv.z, (v.w - mu) * rs * gv.w + bv.w);
}

// ---------------- fp16 TN GEMM body: 128x128 CTA tile, 32x64 warp tiles (4x2 warps), 256 thr ----
// k-chunk = 64 halfs, 3-slot smem ring, one __syncthreads per iter, 2 CTAs/SM => 16 warps/SM.
#define SLOT_B  36864
#define SMEM_GM (4096 + 3 * SLOT_B)

template<int MODE>
__device__ __forceinline__ void gemm_body(
    unsigned char* smem,
    const __half* __restrict__ A, const __half* __restrict__ B, int N, int K,
    const float* __restrict__ bias,
    __half* __restrict__ Hout,
    const int* __restrict__ rl, const float* __restrict__ wl, float* __restrict__ outAdd,
    const float* __restrict__ w2, float* __restrict__ logits,
    int bm, int bn)
{
    const uint32_t su = smem_u32(smem);
    const int tid = threadIdx.x, lane = tid & 31, wid = tid >> 5;
    const int mw = wid >> 1, nw = wid & 1;          // 4x2 warps, warp tile 32x64

    if (MODE == 2) {
        float* w2s = (float*)smem;   // [8][128]
        #pragma unroll
        for (int i = 0; i < 4; i++) {
            int idx = tid + i * 256;
            w2s[idx] = w2[(idx >> 7) * DIM + bn + (idx & 127)];
        }
    }

    float acc[2][8][4] = {};

    auto fill = [&](int chunk, int s) {
        uint32_t sa = su + 4096 + s * SLOT_B;
        uint32_t sb = sa + 18432;
        const __half* Ap = A + (size_t)bm * K + chunk * 64;
        const __half* Bp = B + (size_t)bn * K + chunk * 64;
        #pragma unroll
        for (int i = 0; i < 4; i++) {
            int id = tid + i * 256;                 // 0..1023
            int row = id >> 3, c = (id & 7) * 8;    // halfs
            cp16(sa + row * 144 + c * 2, Ap + (size_t)row * K + c);
            cp16(sb + row * 144 + c * 2, Bp + (size_t)row * K + c);
        }
    };

    const int nk = K >> 6;                          // 64-half K chunks
    fill(0, 0); CPC();
    fill(1, 1); CPC();

    const int lr16 = lane & 15, lhi = (lane >> 4) * 8;

    for (int kt = 0; kt < nk; kt++) {
        int s = kt % 3;
        CPW1();
        __syncthreads();            // slot s ready; slot (kt+2)%3 = (kt-1)%3 free
        if (kt + 2 < nk) fill(kt + 2, (kt + 2) % 3);
        CPC();
        uint32_t sa = su + 4096 + s * SLOT_B;
        uint32_t sb = sa + 18432;
        #pragma unroll
        for (int ks = 0; ks < 4; ks++) {
            const int kk = ks * 16;
            uint32_t af[2][4], bq[4][4];
            #pragma unroll
            for (int mt = 0; mt < 2; mt++)
                ldsm4(af[mt], sa + (mw * 32 + mt * 16 + lr16) * 144 + (kk + lhi) * 2);
            #pragma unroll
            for (int p = 0; p < 4; p++)
                ldsm4(bq[p], sb + (nw * 64 + p * 16 + lr16) * 144 + (kk + lhi) * 2);
            #pragma unroll
            for (int mt = 0; mt < 2; mt++)
                #pragma unroll
                for (int p = 0; p < 4; p++) {
                    mma_f16(acc[mt][2 * p],     af[mt], bq[p][0], bq[p][2]);
                    mma_f16(acc[mt][2 * p + 1], af[mt], bq[p][1], bq[p][3]);
                }
        }
    }

    const int lane4 = lane & 3, lrow = lane >> 2;

    if (MODE == 0) {
        #pragma unroll
        for (int mt = 0; mt < 2; mt++) {
            int r0 = bm + mw * 32 + mt * 16 + lrow;
            #pragma unroll
            for (int nt = 0; nt < 8; nt++) {
                int gn = bn + nw * 64 + nt * 8 + lane4 * 2;
                float* a = acc[mt][nt];
                float b0 = bias[gn], b1 = bias[gn + 1];
                *(__half2*)(Hout + (size_t)r0 * N + gn) =
                    __floats2half2_rn(gelu_tanh(a[0] + b0), gelu_tanh(a[1] + b1));
                *(__half2*)(Hout + (size_t)(r0 + 8) * N + gn) =
                    __floats2half2_rn(gelu_tanh(a[2] + b0), gelu_tanh(a[3] + b1));
            }
        }
    } else if (MODE == 1) {
        #pragma unroll
        for (int mt = 0; mt < 2; mt++) {
            int gr = bm + mw * 32 + mt * 16 + lrow;
            int i0 = rl[gr], i1 = rl[gr + 8];
            float w0 = wl[gr], w1 = wl[gr + 8];
            #pragma unroll
            for (int nt = 0; nt < 8; nt++) {
                int gn = bn + nw * 64 + nt * 8 + lane4 * 2;
                float* a = acc[mt][nt];
                float b0 = bias[gn], b1 = bias[gn + 1];
                // vector atomics (sm_90+): one 8B reduction instead of two 4B -> halves red ops
                atomicAdd((float2*)&outAdd[(size_t)i0 * DIM + gn],
                          make_float2((a[0] + b0) * w0, (a[1] + b1) * w0));
                atomicAdd((float2*)&outAdd[(size_t)i1 * DIM + gn],
                          make_float2((a[2] + b0) * w1, (a[3] + b1) * w1));
            }
        }
    } else {
        const float* w2s = (const float*)smem;
        #pragma unroll
        for (int mt = 0; mt < 2; mt++) {
            #pragma unroll
            for (int half = 0; half < 2; half++) {
                int gr = bm + mw * 32 + mt * 16 + lrow + half * 8;
                float part[NEXP] = {};
                #pragma unroll
                for (int nt = 0; nt < 8; nt++) {
                    int cn = nw * 64 + nt * 8 + lane4 * 2;
                    float h0 = gelu_tanh(acc[mt][nt][2 * half]     + bias[bn + cn]);
                    float h1 = gelu_tanh(acc[mt][nt][2 * half + 1] + bias[bn + cn + 1]);
                    #pragma unroll
                    for (int e = 0; e < NEXP; e++)
                        part[e] += h0 * w2s[e * 128 + cn] + h1 * w2s[e * 128 + cn + 1];
                }
                #pragma unroll
                for (int e = 0; e < NEXP; e++) {
                    part[e] += __shfl_xor_sync(~0u, part[e], 1);
                    part[e] += __shfl_xor_sync(~0u, part[e], 2);
                }
                if (lane4 == 0)
                    #pragma unroll
                    for (int e = 0; e < NEXP; e++)
                        atomicAdd(&logits[gr * NEXP + e], part[e]);
            }
        }
    }
}

// fc1: H = gelu(Y @ fc1^T + b1s) per expert. grid (32, 8, 8)
__global__ void __launch_bounds__(256, 2) gemm_fc1(
    const __half* __restrict__ Y, const __half* __restrict__ fc1,
    const float* __restrict__ b1s, __half* __restrict__ H)
{
    extern __shared__ __align__(16) unsigned char smem[];
    int z = blockIdx.z;
    gemm_body<0>(smem,
        Y + (size_t)z * KQ * DIM, fc1 + (size_t)z * DDIM * DIM, DDIM, DIM,
        b1s + (size_t)z * DDIM,
        H + (size_t)z * KQ * DDIM,
        nullptr, nullptr, nullptr, nullptr, nullptr,
        blockIdx.y * 128, blockIdx.x * 128);
}

// combined fc2 (bid<512) + cap-loss GEMM (bid>=512). grid 1024 x 1D
__global__ void __launch_bounds__(256, 2) gemm_combo(
    const __half* __restrict__ H, const __half* __restrict__ fc2,
    const float* __restrict__ b2s, float* __restrict__ out,
    const __half* __restrict__ xh, const __half* __restrict__ w1h,
    const float* __restrict__ cp_b1, const float* __restrict__ cp_w2)
{
    extern __shared__ __align__(16) unsigned char smem[];
    int bid = blockIdx.x;
    if (bid < 512) {
        int z = bid >> 6, by = (bid >> 3) & 7, bx = bid & 7;
        gemm_body<1>(smem,
            H + (size_t)z * KQ * DDIM, fc2 + (size_t)z * DIM * DDIM, DIM, DDIM,
            b2s + (size_t)z * DIM,
            nullptr,
            g_rlist + z * KQ, g_wlist + z * KQ, out, nullptr, nullptr,
            by * 128, bx * 128);
    } else {
        int t = bid - 512, by = t >> 3, bx = t & 7;
        gemm_body<2>(smem,
            xh, w1h, DIM, DIM,
            cp_b1,
            nullptr,
            nullptr, nullptr, nullptr, cp_w2, g_logits,
            by * 128, bx * 128);
    }
}

__global__ void __launch_bounds__(1024) loss_kernel(const float* __restrict__ cp_b2,
                                                    float* __restrict__ out_loss) {
    int tid = threadIdx.x;
    float s = 0.f;
    for (int i = tid; i < BSZ * NEXP; i += 1024) {
        float l = g_logits[i] + cp_b2[i & 7];
        float sp = fmaxf(l, 0.f) + log1pf(expf(-fabsf(l)));
        s += sp - l * (float)g_mask[i];
    }
    __shared__ float red[1024];
    red[tid] = s;
    __syncthreads();
    for (int o = 512; o; o >>= 1) { if (tid < o) red[tid] += red[tid + o]; __syncthreads(); }
    if (tid == 0) out_loss[0] = red[0] * (1.0f / (BSZ * NEXP));
}

extern "C" void kernel_launch(void* const* d_in, const int* in_sizes, int n_in,
                              void* d_out, int out_size) {
    const float* x     = (const float*)d_in[0];
    const float* Wg    = (const float*)d_in[1];
    const float* cp_w1 = (const float*)d_in[2];
    const float* cp_b1 = (const float*)d_in[3];
    const float* cp_w2 = (const float*)d_in[4];
    const float* cp_b2 = (const float*)d_in[5];
    const float* ln_g  = (const float*)d_in[6];
    const float* ln_b  = (const float*)d_in[7];
    const float* fc1s  = (const float*)d_in[8];
    const float* b1s   = (const float*)d_in[9];
    const float* fc2s  = (const float*)d_in[10];
    const float* b2s   = (const float*)d_in[11];
    float* out = (float*)d_out;

    __half *xh, *w1h, *fc1h, *fc2h, *Yh, *Hh;
    cudaGetSymbolAddress((void**)&xh,   g_xh);
    cudaGetSymbolAddress((void**)&w1h,  g_w1h);
    cudaGetSymbolAddress((void**)&fc1h, g_fc1h);
    cudaGetSymbolAddress((void**)&fc2h, g_fc2h);
    cudaGetSymbolAddress((void**)&Yh,   g_Yh);
    cudaGetSymbolAddress((void**)&Hh,   g_Hh);

    cudaFuncSetAttribute(gemm_fc1,   cudaFuncAttributeMaxDynamicSharedMemorySize, SMEM_GM);
    cudaFuncSetAttribute(gemm_combo, cudaFuncAttributeMaxDynamicSharedMemorySize, SMEM_GM);

    // R14's fastest schedule (R16 consolidation reverted: traffic fused onto a mandatory
    // read is free; relocated traffic is not).
    cvt_kernel<<<2048, 256>>>(fc1s,  fc1h, NEXP * DDIM * DIM / 8);
    cvt_kernel<<<2048, 256>>>(fc2s,  fc2h, NEXP * DIM * DDIM / 8);
    cvt_kernel<<<256,  256>>>(cp_w1, w1h,  DIM * DIM / 8);

    scores_kernel<<<BSZ, 256>>>(x, Wg, xh, out);
    topk_kernel<<<NEXP, 256>>>();
    gather_ln_kernel<<<NEXP * KQ, 256>>>(x, ln_g, ln_b);

    // fc1: per expert H = gelu(Y @ fc1^T + b1s)  (M=1024, N=4096, K=1024)
    gemm_fc1<<<dim3(DDIM / 128, KQ / 128, NEXP), 256, SMEM_GM>>>(Yh, fc1h, b1s, Hh);

    // combined fc2 scatter-add (float2 atomics) + cap-loss logits GEMM
    gemm_combo<<<1024, 256, SMEM_GM>>>(Hh, fc2h, b2s, out, xh, w1h, cp_b1, cp_w2);

    loss_kernel<<<1, 1024>>>(cp_b2, out + (size_t)BSZ * DIM);
    (void)in_sizes; (void)n_in; (void)out_size;
}